// round 14
// baseline (speedup 1.0000x reference)
#include <cuda_runtime.h>
#include <stdint.h>

#define B_   4
#define H_   8
#define N_   2048
#define DV_  64
#define BH_  (B_ * H_)            // 32
#define COLS_ (BH_ * DV_)         // 2048 sort columns
#define OUT_ELEMS (BH_ * (size_t)N_ * DV_)
#define ATTN_ELEMS ((size_t)BH_ * N_ * N_)

// ---------------- scratch ----------------------------------------------------
__device__ uint32_t g_key [COLS_ * N_];   // sortable v, [bh][d][i]
__device__ float    g_vs  [COLS_ * N_];   // sorted values [bh][d][r]
__device__ uint16_t g_inv [COLS_ * N_];   // rank of orig index i
__device__ uint16_t g_p0  [BH_  * N_];    // p_0[r]

__device__ __forceinline__ uint32_t f2sort(float x) {
    uint32_t u = __float_as_uint(x);
    return u ^ ((u & 0x80000000u) ? 0xFFFFFFFFu : 0x80000000u);
}
__device__ __forceinline__ float sort2f(uint32_t u) {
    u ^= (u & 0x80000000u) ? 0x80000000u : 0xFFFFFFFFu;
    return __uint_as_float(u);
}
__device__ __forceinline__ uint64_t cmpsel(uint64_t a, uint64_t y, bool keepmin) {
    return ((y < a) == keepmin) ? y : a;
}

// ---------------- 1) transpose v [bh][i][d] -> g_key [bh][d][i] --------------
__global__ void k_transpose_in(const float* __restrict__ v) {
    __shared__ float tile[32][33];
    int bh = blockIdx.z;
    int i0 = blockIdx.x * 32;
    int d0 = blockIdx.y * 32;
    int tx = threadIdx.x, ty = threadIdx.y;     // (32,8)
    const float* src = v + (size_t)bh * N_ * DV_;
#pragma unroll
    for (int r = 0; r < 32; r += 8)
        tile[ty + r][tx] = src[(size_t)(i0 + ty + r) * DV_ + (d0 + tx)];
    __syncthreads();
    uint32_t* dst = g_key + (size_t)bh * DV_ * N_;
#pragma unroll
    for (int r = 0; r < 32; r += 8)
        dst[(size_t)(d0 + ty + r) * N_ + (i0 + tx)] = f2sort(tile[tx][ty + r]);
}

// ---------------- bitonic merge tail, compile-time J -------------------------
template<int J>
__device__ __forceinline__ void merge_tail(uint64_t* x, int lane, int warp, int k) {
    if constexpr (J >= 8) {
        constexpr int LJ = J / 8;
#pragma unroll
        for (int r = 0; r < 8; r++) {
            int e = warp * 256 + lane * 8 + r;
            uint64_t y = __shfl_xor_sync(0xffffffffu, x[r], LJ);
            bool keepmin = (((lane & LJ) == 0) == ((e & k) == 0));
            x[r] = cmpsel(x[r], y, keepmin);
        }
    } else {
#pragma unroll
        for (int r = 0; r < 8; r++) {
            if ((r & J) == 0) {
                int e = warp * 256 + lane * 8 + r;
                bool up = ((e & k) == 0);
                uint64_t a = x[r], c = x[r + J];
                uint64_t mn = a < c ? a : c;
                uint64_t mx = a < c ? c : a;
                x[r]     = up ? mn : mx;
                x[r + J] = up ? mx : mn;
            }
        }
    }
    if constexpr (J > 1) merge_tail<J / 2>(x, lane, warp, k);
}

__device__ __forceinline__ void smem_stage(uint64_t* x, uint64_t* s,
                                           int g, int ebase, int j, int k) {
#pragma unroll
    for (int r = 0; r < 8; r += 2)
        *reinterpret_cast<ulonglong2*>(&s[10 * g + r]) =
            make_ulonglong2(x[r], x[r + 1]);
    __syncthreads();
    const int gp = g ^ (j >> 3);
    const bool upperbit = ((g & (j >> 3)) == 0);
    const bool kbit     = ((ebase & k) == 0);
    const bool keepmin  = (upperbit == kbit);
    uint64_t y[8];
#pragma unroll
    for (int r = 0; r < 8; r += 2) {
        ulonglong2 t2 = *reinterpret_cast<const ulonglong2*>(&s[10 * gp + r]);
        y[r] = t2.x; y[r + 1] = t2.y;
    }
#pragma unroll
    for (int r = 0; r < 8; r++)
        x[r] = cmpsel(x[r], y[r], keepmin);
    __syncthreads();
}

// ---------------- 2) fused: bitonic sort + attn zero-fill --------------------
// col = col_base + blockIdx.x; each block fills its own 256KB attn slice,
// spread across the sort phases (R7/R10 structure).
__global__ __launch_bounds__(256) void k_sortfill(float* __restrict__ attn,
                                                  int col_base) {
    const int col  = col_base + blockIdx.x;
    const int t    = threadIdx.x;
    const int lane = t & 31;
    const int warp = t >> 5;
    const int g    = warp * 32 + lane;
    const int ebase = g * 8;

    float4* __restrict__ fbase =
        reinterpret_cast<float4*>(attn) + (size_t)col * 16384 + t;
    const float4 z = make_float4(0.f, 0.f, 0.f, 0.f);
#define FILL4(c)                                                     \
    {  _Pragma("unroll")                                             \
       for (int s_ = 0; s_ < 4; s_++)                                \
           __stcs(fbase + (c) * 1024 + s_ * 256, z); }

    const uint32_t* __restrict__ key = g_key + (size_t)col * N_;

    FILL4(0)

    uint64_t x[8];
    {
        uint4 k0 = *reinterpret_cast<const uint4*>(key + ebase);
        uint4 k1 = *reinterpret_cast<const uint4*>(key + ebase + 4);
        x[0] = ((uint64_t)k0.x << 32) | (uint32_t)(ebase + 0);
        x[1] = ((uint64_t)k0.y << 32) | (uint32_t)(ebase + 1);
        x[2] = ((uint64_t)k0.z << 32) | (uint32_t)(ebase + 2);
        x[3] = ((uint64_t)k0.w << 32) | (uint32_t)(ebase + 3);
        x[4] = ((uint64_t)k1.x << 32) | (uint32_t)(ebase + 4);
        x[5] = ((uint64_t)k1.y << 32) | (uint32_t)(ebase + 5);
        x[6] = ((uint64_t)k1.z << 32) | (uint32_t)(ebase + 6);
        x[7] = ((uint64_t)k1.w << 32) | (uint32_t)(ebase + 7);
    }

    __shared__ uint64_t s[10 * 256];   // 20KB

    merge_tail<1>  (x, lane, warp, 2);
    merge_tail<2>  (x, lane, warp, 4);
    merge_tail<4>  (x, lane, warp, 8);
    FILL4(1)
    merge_tail<8>  (x, lane, warp, 16);
    FILL4(2)
    merge_tail<16> (x, lane, warp, 32);
    FILL4(3)
    merge_tail<32> (x, lane, warp, 64);
    FILL4(4)
    merge_tail<64> (x, lane, warp, 128);
    FILL4(5)
    merge_tail<128>(x, lane, warp, 256);
    FILL4(6)

    smem_stage(x, s, g, ebase, 256, 512);
    FILL4(7)
    merge_tail<128>(x, lane, warp, 512);
    FILL4(8)
    smem_stage(x, s, g, ebase, 512, 1024);
    FILL4(9)
    smem_stage(x, s, g, ebase, 256, 1024);
    FILL4(10)
    merge_tail<128>(x, lane, warp, 1024);
    FILL4(11)
    smem_stage(x, s, g, ebase, 1024, 2048);
    FILL4(12)
    smem_stage(x, s, g, ebase, 512, 2048);
    FILL4(13)
    smem_stage(x, s, g, ebase, 256, 2048);
    FILL4(14)
    merge_tail<128>(x, lane, warp, 2048);
    FILL4(15)

    // epilogue
    const int d  = col & 63;
    const int bh = col >> 6;
    float*    __restrict__ vs  = g_vs  + (size_t)col * N_;
    uint16_t* __restrict__ inv = g_inv + (size_t)col * N_;
    {
        float4 f0 = make_float4(sort2f((uint32_t)(x[0] >> 32)),
                                sort2f((uint32_t)(x[1] >> 32)),
                                sort2f((uint32_t)(x[2] >> 32)),
                                sort2f((uint32_t)(x[3] >> 32)));
        float4 f1 = make_float4(sort2f((uint32_t)(x[4] >> 32)),
                                sort2f((uint32_t)(x[5] >> 32)),
                                sort2f((uint32_t)(x[6] >> 32)),
                                sort2f((uint32_t)(x[7] >> 32)));
        *reinterpret_cast<float4*>(vs + ebase)     = f0;
        *reinterpret_cast<float4*>(vs + ebase + 4) = f1;
    }
#pragma unroll
    for (int r = 0; r < 8; r++) {
        uint32_t idx = (uint32_t)x[r];
        inv[idx] = (uint16_t)(ebase + r);
        if (d == 0) g_p0[bh * N_ + ebase + r] = (uint16_t)idx;
    }
#undef FILL4
}

// ---------------- 3) gather+transpose + scatter, per bh-half (R10 kernel) ----
// grid (16, NH+1): y<NH -> gather (bh=bh_base+y, d-group=x*4);
// y==NH -> scatter rows of this half (16 blocks x NH*128 rows).
__global__ __launch_bounds__(512) void k_gather_t(float* __restrict__ out,
                                                  float* __restrict__ attn,
                                                  int bh_base, int nh) {
    const int t = threadIdx.x;
    if (blockIdx.y == (unsigned)nh) {   // scatter: attn[bh][i][p0[inv1[i]]] = 1
        int rows = nh * N_ / 16;        // per block
        int base = bh_base * N_ + blockIdx.x * rows;
        for (int m = t; m < rows; m += 512) {
            int gid = base + m;
            int bh = gid >> 11;
            int i  = gid & (N_ - 1);
            int j    = g_inv[(size_t)(bh * DV_ + 1) * N_ + i];
            int aidx = g_p0[bh * N_ + j];
            attn[(size_t)gid * N_ + aidx] = 1.0f;
        }
        return;
    }
    const int bh = bh_base + blockIdx.y;
    const int d0 = blockIdx.x * 4;

    __shared__ float    svs [4 * N_];        // 32KB
    __shared__ uint16_t sinv[4][512 + 8];

#pragma unroll
    for (int d = 0; d < 4; d++)
        for (int i = t; i < N_; i += 512)
            svs[d * N_ + i] = g_vs[(size_t)(bh * DV_ + d0 + d) * N_ + i];

    const int dd = t & 3;
    const int iw = t >> 2;
    float* obase = out + (size_t)bh * N_ * DV_ + d0 + dd;

    for (int it = 0; it < 4; it++) {
        const int i0 = it * 512;
        __syncthreads();
#pragma unroll
        for (int d = 0; d < 4; d++) {
            int d1 = (d0 + d + 1) & 63;
            sinv[d][t] = g_inv[(size_t)(bh * DV_ + d1) * N_ + i0 + t];
        }
        __syncthreads();
#pragma unroll
        for (int rr = 0; rr < 4; rr++) {
            int ii = rr * 128 + iw;
            int rank = sinv[dd][ii];
            obase[(size_t)(i0 + ii) * DV_] = svs[dd * N_ + rank];
        }
    }
}

// ---------------- launch: fork/join pipeline over bh-halves -------------------
extern "C" void kernel_launch(void* const* d_in, const int* in_sizes, int n_in,
                              void* d_out, int out_size) {
    (void)in_sizes; (void)n_in; (void)out_size;
    const float* v = (const float*)d_in[2];      // order: q, k, v
    float* out  = (float*)d_out;
    float* attn = out + OUT_ELEMS;

    static cudaStream_t s1 = nullptr;
    static cudaEvent_t evH0 = nullptr, evJoin = nullptr;
    if (s1 == nullptr) {   // one-time resource init (first call is non-capture)
        cudaStreamCreateWithFlags(&s1, cudaStreamNonBlocking);
        cudaEventCreateWithFlags(&evH0, cudaEventDisableTiming);
        cudaEventCreateWithFlags(&evJoin, cudaEventDisableTiming);
    }

    const int HALF = COLS_ / 2;   // 1024 columns = bh 0..15

    k_transpose_in <<<dim3(N_ / 32, DV_ / 32, BH_), dim3(32, 8)>>>(v);

    // half 0 sort (+fill of its attn slice)
    k_sortfill <<<HALF, 256>>>(attn, 0);
    cudaEventRecord(evH0, 0);

    // half 1 sort on main stream; half 0 gather+scatter concurrently on s1
    k_sortfill <<<HALF, 256>>>(attn, HALF);

    cudaStreamWaitEvent(s1, evH0, 0);
    k_gather_t <<<dim3(16, 17), 512, 0, s1>>>(out, attn, 0, 16);
    cudaEventRecord(evJoin, s1);

    // half 1 gather+scatter on main stream, then join s1 back
    k_gather_t <<<dim3(16, 17), 512>>>(out, attn, 16, 16);
    cudaStreamWaitEvent(0, evJoin, 0);
}

// round 15
// speedup vs baseline: 1.0122x; 1.0122x over previous
#include <cuda_runtime.h>
#include <stdint.h>

#define B_   4
#define H_   8
#define N_   2048
#define DV_  64
#define BH_  (B_ * H_)            // 32
#define COLS_ (BH_ * DV_)         // 2048 sort columns
#define OUT_ELEMS (BH_ * (size_t)N_ * DV_)
#define ATTN_ELEMS ((size_t)BH_ * N_ * N_)

// attn fill split: sortfill fills first 448MB (2048 blocks x 224KB),
// transpose fills last 64MB (4096 blocks x 16KB).
#define SORT_FILL_F4   14336u        // float4 per sortfill block (224KB)
#define TRANS_FILL_BASE 29360128u    // float4 offset of transpose region

// ---------------- scratch ----------------------------------------------------
__device__ uint32_t g_key [COLS_ * N_];   // sortable v, [bh][d][i]
__device__ float    g_vs  [COLS_ * N_];   // sorted values [bh][d][r]
__device__ uint16_t g_inv [COLS_ * N_];   // rank of orig index i
__device__ uint16_t g_p0  [BH_  * N_];    // p_0[r]

__device__ __forceinline__ uint32_t f2sort(float x) {
    uint32_t u = __float_as_uint(x);
    return u ^ ((u & 0x80000000u) ? 0xFFFFFFFFu : 0x80000000u);
}
__device__ __forceinline__ float sort2f(uint32_t u) {
    u ^= (u & 0x80000000u) ? 0x80000000u : 0xFFFFFFFFu;
    return __uint_as_float(u);
}
__device__ __forceinline__ uint64_t cmpsel(uint64_t a, uint64_t y, bool keepmin) {
    return ((y < a) == keepmin) ? y : a;
}

// ---------------- 1) transpose v -> g_key, + 16KB attn fill per block --------
__global__ void k_transpose_in(const float* __restrict__ v,
                               float* __restrict__ attn) {
    __shared__ float tile[32][33];
    int bh = blockIdx.z;
    int i0 = blockIdx.x * 32;
    int d0 = blockIdx.y * 32;
    int tx = threadIdx.x, ty = threadIdx.y;     // (32,8)
    const float* src = v + (size_t)bh * N_ * DV_;
#pragma unroll
    for (int r = 0; r < 32; r += 8)
        tile[ty + r][tx] = src[(size_t)(i0 + ty + r) * DV_ + (d0 + tx)];

    // fill 16KB of attn tail region (last 64MB), fire-and-forget
    {
        int blin = (blockIdx.z * 2 + blockIdx.y) * 64 + blockIdx.x;   // 0..4095
        int t = ty * 32 + tx;                                         // 0..255
        float4* fb = reinterpret_cast<float4*>(attn)
                   + (size_t)TRANS_FILL_BASE + (size_t)blin * 1024 + t;
        const float4 z = make_float4(0.f, 0.f, 0.f, 0.f);
#pragma unroll
        for (int s_ = 0; s_ < 4; s_++) __stcs(fb + s_ * 256, z);
    }

    __syncthreads();
    uint32_t* dst = g_key + (size_t)bh * DV_ * N_;
#pragma unroll
    for (int r = 0; r < 32; r += 8)
        dst[(size_t)(d0 + ty + r) * N_ + (i0 + tx)] = f2sort(tile[tx][ty + r]);
}

// ---------------- bitonic merge tail, compile-time J -------------------------
template<int J>
__device__ __forceinline__ void merge_tail(uint64_t* x, int lane, int warp, int k) {
    if constexpr (J >= 8) {
        constexpr int LJ = J / 8;
#pragma unroll
        for (int r = 0; r < 8; r++) {
            int e = warp * 256 + lane * 8 + r;
            uint64_t y = __shfl_xor_sync(0xffffffffu, x[r], LJ);
            bool keepmin = (((lane & LJ) == 0) == ((e & k) == 0));
            x[r] = cmpsel(x[r], y, keepmin);
        }
    } else {
#pragma unroll
        for (int r = 0; r < 8; r++) {
            if ((r & J) == 0) {
                int e = warp * 256 + lane * 8 + r;
                bool up = ((e & k) == 0);
                uint64_t a = x[r], c = x[r + J];
                uint64_t mn = a < c ? a : c;
                uint64_t mx = a < c ? c : a;
                x[r]     = up ? mn : mx;
                x[r + J] = up ? mx : mn;
            }
        }
    }
    if constexpr (J > 1) merge_tail<J / 2>(x, lane, warp, k);
}

__device__ __forceinline__ void smem_stage(uint64_t* x, uint64_t* s,
                                           int g, int ebase, int j, int k) {
#pragma unroll
    for (int r = 0; r < 8; r += 2)
        *reinterpret_cast<ulonglong2*>(&s[10 * g + r]) =
            make_ulonglong2(x[r], x[r + 1]);
    __syncthreads();
    const int gp = g ^ (j >> 3);
    const bool upperbit = ((g & (j >> 3)) == 0);
    const bool kbit     = ((ebase & k) == 0);
    const bool keepmin  = (upperbit == kbit);
    uint64_t y[8];
#pragma unroll
    for (int r = 0; r < 8; r += 2) {
        ulonglong2 t2 = *reinterpret_cast<const ulonglong2*>(&s[10 * gp + r]);
        y[r] = t2.x; y[r + 1] = t2.y;
    }
#pragma unroll
    for (int r = 0; r < 8; r++)
        x[r] = cmpsel(x[r], y[r], keepmin);
    __syncthreads();
}

// ---------------- 2) fused: bitonic sort + 224KB attn fill per block ---------
__global__ __launch_bounds__(256) void k_sortfill(float* __restrict__ attn) {
    const int col  = blockIdx.x;
    const int t    = threadIdx.x;
    const int lane = t & 31;
    const int warp = t >> 5;
    const int g    = warp * 32 + lane;
    const int ebase = g * 8;

    float4* __restrict__ fbase =
        reinterpret_cast<float4*>(attn) + (size_t)col * SORT_FILL_F4 + t;
    const float4 z = make_float4(0.f, 0.f, 0.f, 0.f);
#define FILL4(c)                                                     \
    {  _Pragma("unroll")                                             \
       for (int s_ = 0; s_ < 4; s_++)                                \
           __stcs(fbase + (c) * 1024 + s_ * 256, z); }

    const uint32_t* __restrict__ key = g_key + (size_t)col * N_;

    FILL4(0)

    uint64_t x[8];
    {
        uint4 k0 = *reinterpret_cast<const uint4*>(key + ebase);
        uint4 k1 = *reinterpret_cast<const uint4*>(key + ebase + 4);
        x[0] = ((uint64_t)k0.x << 32) | (uint32_t)(ebase + 0);
        x[1] = ((uint64_t)k0.y << 32) | (uint32_t)(ebase + 1);
        x[2] = ((uint64_t)k0.z << 32) | (uint32_t)(ebase + 2);
        x[3] = ((uint64_t)k0.w << 32) | (uint32_t)(ebase + 3);
        x[4] = ((uint64_t)k1.x << 32) | (uint32_t)(ebase + 4);
        x[5] = ((uint64_t)k1.y << 32) | (uint32_t)(ebase + 5);
        x[6] = ((uint64_t)k1.z << 32) | (uint32_t)(ebase + 6);
        x[7] = ((uint64_t)k1.w << 32) | (uint32_t)(ebase + 7);
    }

    __shared__ uint64_t s[10 * 256];   // 20KB

    merge_tail<1>  (x, lane, warp, 2);
    merge_tail<2>  (x, lane, warp, 4);
    merge_tail<4>  (x, lane, warp, 8);
    FILL4(1)
    merge_tail<8>  (x, lane, warp, 16);
    FILL4(2)
    merge_tail<16> (x, lane, warp, 32);
    FILL4(3)
    merge_tail<32> (x, lane, warp, 64);
    FILL4(4)
    merge_tail<64> (x, lane, warp, 128);
    FILL4(5)
    merge_tail<128>(x, lane, warp, 256);
    FILL4(6)

    smem_stage(x, s, g, ebase, 256, 512);
    FILL4(7)
    merge_tail<128>(x, lane, warp, 512);
    FILL4(8)
    smem_stage(x, s, g, ebase, 512, 1024);
    FILL4(9)
    smem_stage(x, s, g, ebase, 256, 1024);
    FILL4(10)
    merge_tail<128>(x, lane, warp, 1024);
    FILL4(11)
    smem_stage(x, s, g, ebase, 1024, 2048);
    FILL4(12)
    smem_stage(x, s, g, ebase, 512, 2048);
    FILL4(13)
    smem_stage(x, s, g, ebase, 256, 2048);
    merge_tail<128>(x, lane, warp, 2048);

    // epilogue
    const int d  = col & 63;
    const int bh = col >> 6;
    float*    __restrict__ vs  = g_vs  + (size_t)col * N_;
    uint16_t* __restrict__ inv = g_inv + (size_t)col * N_;
    {
        float4 f0 = make_float4(sort2f((uint32_t)(x[0] >> 32)),
                                sort2f((uint32_t)(x[1] >> 32)),
                                sort2f((uint32_t)(x[2] >> 32)),
                                sort2f((uint32_t)(x[3] >> 32)));
        float4 f1 = make_float4(sort2f((uint32_t)(x[4] >> 32)),
                                sort2f((uint32_t)(x[5] >> 32)),
                                sort2f((uint32_t)(x[6] >> 32)),
                                sort2f((uint32_t)(x[7] >> 32)));
        *reinterpret_cast<float4*>(vs + ebase)     = f0;
        *reinterpret_cast<float4*>(vs + ebase + 4) = f1;
    }
#pragma unroll
    for (int r = 0; r < 8; r++) {
        uint32_t idx = (uint32_t)x[r];
        inv[idx] = (uint16_t)(ebase + r);
        if (d == 0) g_p0[bh * N_ + ebase + r] = (uint16_t)idx;
    }
#undef FILL4
}

// ---------------- 3) gather+transpose, fully-preloaded smem, no loop syncs ---
// grid (16, 33): y<32 -> gather (bh=y, d-group=x*4); y==32 -> attn scatter.
// Stage 4 vs columns (32KB) AND 4 full inv columns (16KB) up front; single
// sync; then 16 independent iterations (high MLP, zero barriers).
__global__ __launch_bounds__(512) void k_gather_t(float* __restrict__ out,
                                                  float* __restrict__ attn) {
    const int t = threadIdx.x;
    if (blockIdx.y == BH_) {   // attn scatter: attn[bh][i][p0[inv1[i]]] = 1
        int base = blockIdx.x * 4096;
        for (int m = t; m < 4096; m += 512) {
            int gid = base + m;
            int bh = gid >> 11;
            int i  = gid & (N_ - 1);
            int j    = g_inv[(size_t)(bh * DV_ + 1) * N_ + i];
            int aidx = g_p0[bh * N_ + j];
            attn[(size_t)gid * N_ + aidx] = 1.0f;
        }
        return;
    }
    const int bh = blockIdx.y;
    const int d0 = blockIdx.x * 4;

    __shared__ float    svs [4 * N_];   // 32KB
    __shared__ uint16_t sinv[4 * N_];   // 16KB

#pragma unroll
    for (int d = 0; d < 4; d++) {
        const float* vsp = g_vs + (size_t)(bh * DV_ + d0 + d) * N_;
        for (int i = t; i < N_; i += 512)
            svs[d * N_ + i] = vsp[i];
    }
#pragma unroll
    for (int d = 0; d < 4; d++) {
        int d1 = (d0 + d + 1) & 63;
        const uint16_t* ivp = g_inv + (size_t)(bh * DV_ + d1) * N_;
        for (int i = t; i < N_; i += 512)
            sinv[d * N_ + i] = ivp[i];
    }
    __syncthreads();

    const int dd = t & 3;          // this thread's d
    const int iw = t >> 2;         // 0..127
    float* obase = out + (size_t)bh * N_ * DV_ + d0 + dd;
    const float*    svd = svs  + dd * N_;
    const uint16_t* ivd = sinv + dd * N_;

#pragma unroll
    for (int rr = 0; rr < 16; rr++) {
        int ii = rr * 128 + iw;
        int rank = ivd[ii];
        obase[(size_t)ii * DV_] = svd[rank];
    }
}

// ---------------- launch ------------------------------------------------------
extern "C" void kernel_launch(void* const* d_in, const int* in_sizes, int n_in,
                              void* d_out, int out_size) {
    (void)in_sizes; (void)n_in; (void)out_size;
    const float* v = (const float*)d_in[2];      // order: q, k, v
    float* out  = (float*)d_out;
    float* attn = out + OUT_ELEMS;

    k_transpose_in <<<dim3(N_ / 32, DV_ / 32, BH_), dim3(32, 8)>>>(v, attn);
    k_sortfill     <<<COLS_, 256>>>(attn);
    k_gather_t     <<<dim3(16, BH_ + 1), 512>>>(out, attn);
}

// round 16
// speedup vs baseline: 1.0545x; 1.0418x over previous
#include <cuda_runtime.h>
#include <stdint.h>

#define B_   4
#define H_   8
#define N_   2048
#define DV_  64
#define BH_  (B_ * H_)            // 32
#define COLS_ (BH_ * DV_)         // 2048 sort columns
#define OUT_ELEMS (BH_ * (size_t)N_ * DV_)
#define ATTN_ELEMS ((size_t)BH_ * N_ * N_)

// ---------------- scratch ----------------------------------------------------
__device__ uint32_t g_key [COLS_ * N_];   // sortable v, [bh][d][i]
__device__ float    g_vs  [COLS_ * N_];   // sorted values [bh][d][r]
__device__ uint16_t g_inv [COLS_ * N_];   // rank of orig index i
__device__ uint16_t g_p0  [BH_  * N_];    // p_0[r]

__device__ __forceinline__ uint32_t f2sort(float x) {
    uint32_t u = __float_as_uint(x);
    return u ^ ((u & 0x80000000u) ? 0xFFFFFFFFu : 0x80000000u);
}
__device__ __forceinline__ float sort2f(uint32_t u) {
    u ^= (u & 0x80000000u) ? 0x80000000u : 0xFFFFFFFFu;
    return __uint_as_float(u);
}
__device__ __forceinline__ uint64_t cmpsel(uint64_t a, uint64_t y, bool keepmin) {
    return ((y < a) == keepmin) ? y : a;
}

// ---------------- 1) transpose v [bh][i][d] -> g_key [bh][d][i] --------------
__global__ void k_transpose_in(const float* __restrict__ v) {
    __shared__ float tile[32][33];
    int bh = blockIdx.z;
    int i0 = blockIdx.x * 32;
    int d0 = blockIdx.y * 32;
    int tx = threadIdx.x, ty = threadIdx.y;     // (32,8)
    const float* src = v + (size_t)bh * N_ * DV_;
#pragma unroll
    for (int r = 0; r < 32; r += 8)
        tile[ty + r][tx] = src[(size_t)(i0 + ty + r) * DV_ + (d0 + tx)];
    __syncthreads();
    uint32_t* dst = g_key + (size_t)bh * DV_ * N_;
#pragma unroll
    for (int r = 0; r < 32; r += 8)
        dst[(size_t)(d0 + ty + r) * N_ + (i0 + tx)] = f2sort(tile[tx][ty + r]);
}

// ---------------- bitonic merge tail, compile-time J -------------------------
template<int J>
__device__ __forceinline__ void merge_tail(uint64_t* x, int lane, int warp, int k) {
    if constexpr (J >= 8) {
        constexpr int LJ = J / 8;
#pragma unroll
        for (int r = 0; r < 8; r++) {
            int e = warp * 256 + lane * 8 + r;
            uint64_t y = __shfl_xor_sync(0xffffffffu, x[r], LJ);
            bool keepmin = (((lane & LJ) == 0) == ((e & k) == 0));
            x[r] = cmpsel(x[r], y, keepmin);
        }
    } else {
#pragma unroll
        for (int r = 0; r < 8; r++) {
            if ((r & J) == 0) {
                int e = warp * 256 + lane * 8 + r;
                bool up = ((e & k) == 0);
                uint64_t a = x[r], c = x[r + J];
                uint64_t mn = a < c ? a : c;
                uint64_t mx = a < c ? c : a;
                x[r]     = up ? mn : mx;
                x[r + J] = up ? mx : mn;
            }
        }
    }
    if constexpr (J > 1) merge_tail<J / 2>(x, lane, warp, k);
}

__device__ __forceinline__ void smem_stage(uint64_t* x, uint64_t* s,
                                           int g, int ebase, int j, int k) {
#pragma unroll
    for (int r = 0; r < 8; r += 2)
        *reinterpret_cast<ulonglong2*>(&s[10 * g + r]) =
            make_ulonglong2(x[r], x[r + 1]);
    __syncthreads();
    const int gp = g ^ (j >> 3);
    const bool upperbit = ((g & (j >> 3)) == 0);
    const bool kbit     = ((ebase & k) == 0);
    const bool keepmin  = (upperbit == kbit);
    uint64_t y[8];
#pragma unroll
    for (int r = 0; r < 8; r += 2) {
        ulonglong2 t2 = *reinterpret_cast<const ulonglong2*>(&s[10 * gp + r]);
        y[r] = t2.x; y[r + 1] = t2.y;
    }
#pragma unroll
    for (int r = 0; r < 8; r++)
        x[r] = cmpsel(x[r], y[r], keepmin);
    __syncthreads();
}

// ---------------- 2) fused: bitonic sort + attn zero-fill (R10 exact) --------
__global__ __launch_bounds__(256) void k_sortfill(float* __restrict__ attn) {
    const int col  = blockIdx.x;
    const int t    = threadIdx.x;
    const int lane = t & 31;
    const int warp = t >> 5;
    const int g    = warp * 32 + lane;
    const int ebase = g * 8;

    float4* __restrict__ fbase =
        reinterpret_cast<float4*>(attn) + (size_t)col * 16384 + t;
    const float4 z = make_float4(0.f, 0.f, 0.f, 0.f);
#define FILL4(c)                                                     \
    {  _Pragma("unroll")                                             \
       for (int s_ = 0; s_ < 4; s_++)                                \
           __stcs(fbase + (c) * 1024 + s_ * 256, z); }

    const uint32_t* __restrict__ key = g_key + (size_t)col * N_;

    FILL4(0)

    uint64_t x[8];
    {
        uint4 k0 = *reinterpret_cast<const uint4*>(key + ebase);
        uint4 k1 = *reinterpret_cast<const uint4*>(key + ebase + 4);
        x[0] = ((uint64_t)k0.x << 32) | (uint32_t)(ebase + 0);
        x[1] = ((uint64_t)k0.y << 32) | (uint32_t)(ebase + 1);
        x[2] = ((uint64_t)k0.z << 32) | (uint32_t)(ebase + 2);
        x[3] = ((uint64_t)k0.w << 32) | (uint32_t)(ebase + 3);
        x[4] = ((uint64_t)k1.x << 32) | (uint32_t)(ebase + 4);
        x[5] = ((uint64_t)k1.y << 32) | (uint32_t)(ebase + 5);
        x[6] = ((uint64_t)k1.z << 32) | (uint32_t)(ebase + 6);
        x[7] = ((uint64_t)k1.w << 32) | (uint32_t)(ebase + 7);
    }

    __shared__ uint64_t s[10 * 256];   // 20KB

    merge_tail<1>  (x, lane, warp, 2);
    merge_tail<2>  (x, lane, warp, 4);
    merge_tail<4>  (x, lane, warp, 8);
    FILL4(1)
    merge_tail<8>  (x, lane, warp, 16);
    FILL4(2)
    merge_tail<16> (x, lane, warp, 32);
    FILL4(3)
    merge_tail<32> (x, lane, warp, 64);
    FILL4(4)
    merge_tail<64> (x, lane, warp, 128);
    FILL4(5)
    merge_tail<128>(x, lane, warp, 256);
    FILL4(6)

    smem_stage(x, s, g, ebase, 256, 512);
    FILL4(7)
    merge_tail<128>(x, lane, warp, 512);
    FILL4(8)
    smem_stage(x, s, g, ebase, 512, 1024);
    FILL4(9)
    smem_stage(x, s, g, ebase, 256, 1024);
    FILL4(10)
    merge_tail<128>(x, lane, warp, 1024);
    FILL4(11)
    smem_stage(x, s, g, ebase, 1024, 2048);
    FILL4(12)
    smem_stage(x, s, g, ebase, 512, 2048);
    FILL4(13)
    smem_stage(x, s, g, ebase, 256, 2048);
    FILL4(14)
    merge_tail<128>(x, lane, warp, 2048);
    FILL4(15)

    // epilogue
    const int d  = col & 63;
    const int bh = col >> 6;
    float*    __restrict__ vs  = g_vs  + (size_t)col * N_;
    uint16_t* __restrict__ inv = g_inv + (size_t)col * N_;
    {
        float4 f0 = make_float4(sort2f((uint32_t)(x[0] >> 32)),
                                sort2f((uint32_t)(x[1] >> 32)),
                                sort2f((uint32_t)(x[2] >> 32)),
                                sort2f((uint32_t)(x[3] >> 32)));
        float4 f1 = make_float4(sort2f((uint32_t)(x[4] >> 32)),
                                sort2f((uint32_t)(x[5] >> 32)),
                                sort2f((uint32_t)(x[6] >> 32)),
                                sort2f((uint32_t)(x[7] >> 32)));
        *reinterpret_cast<float4*>(vs + ebase)     = f0;
        *reinterpret_cast<float4*>(vs + ebase + 4) = f1;
    }
#pragma unroll
    for (int r = 0; r < 8; r++) {
        uint32_t idx = (uint32_t)x[r];
        inv[idx] = (uint16_t)(ebase + r);
        if (d == 0) g_p0[bh * N_ + ebase + r] = (uint16_t)idx;
    }
#undef FILL4
}

// ---------------- 3) gather+transpose, fully-preloaded smem ------------------
// grid (16, 33): y<32 -> gather (bh=y, d-group=x*4); y==32 -> attn scatter.
// Stage 4 vs columns (32KB) + 4 full inv columns (16KB), ONE sync, then 16
// independent iterations (no barriers in the gather loop).
__global__ __launch_bounds__(512) void k_gather_t(float* __restrict__ out,
                                                  float* __restrict__ attn) {
    const int t = threadIdx.x;
    if (blockIdx.y == BH_) {   // attn scatter: attn[bh][i][p0[inv1[i]]] = 1
        int base = blockIdx.x * 4096;
        for (int m = t; m < 4096; m += 512) {
            int gid = base + m;
            int bh = gid >> 11;
            int i  = gid & (N_ - 1);
            int j    = g_inv[(size_t)(bh * DV_ + 1) * N_ + i];
            int aidx = g_p0[bh * N_ + j];
            attn[(size_t)gid * N_ + aidx] = 1.0f;
        }
        return;
    }
    const int bh = blockIdx.y;
    const int d0 = blockIdx.x * 4;

    __shared__ float    svs [4 * N_];   // 32KB
    __shared__ uint16_t sinv[4 * N_];   // 16KB

#pragma unroll
    for (int d = 0; d < 4; d++) {
        const float* vsp = g_vs + (size_t)(bh * DV_ + d0 + d) * N_;
        for (int i = t; i < N_; i += 512)
            svs[d * N_ + i] = vsp[i];
    }
#pragma unroll
    for (int d = 0; d < 4; d++) {
        int d1 = (d0 + d + 1) & 63;
        const uint16_t* ivp = g_inv + (size_t)(bh * DV_ + d1) * N_;
        for (int i = t; i < N_; i += 512)
            sinv[d * N_ + i] = ivp[i];
    }
    __syncthreads();

    const int dd = t & 3;          // this thread's d
    const int iw = t >> 2;         // 0..127
    float* obase = out + (size_t)bh * N_ * DV_ + d0 + dd;
    const float*    svd = svs  + dd * N_;
    const uint16_t* ivd = sinv + dd * N_;

#pragma unroll
    for (int rr = 0; rr < 16; rr++) {
        int ii = rr * 128 + iw;
        int rank = ivd[ii];
        obase[(size_t)ii * DV_] = svd[rank];
    }
}

// ---------------- launch ------------------------------------------------------
extern "C" void kernel_launch(void* const* d_in, const int* in_sizes, int n_in,
                              void* d_out, int out_size) {
    (void)in_sizes; (void)n_in; (void)out_size;
    const float* v = (const float*)d_in[2];      // order: q, k, v
    float* out  = (float*)d_out;
    float* attn = out + OUT_ELEMS;

    k_transpose_in <<<dim3(N_ / 32, DV_ / 32, BH_), dim3(32, 8)>>>(v);
    k_sortfill     <<<COLS_, 256>>>(attn);
    k_gather_t     <<<dim3(16, BH_ + 1), 512>>>(out, attn);
}

// round 17
// speedup vs baseline: 1.0608x; 1.0060x over previous
#include <cuda_runtime.h>
#include <stdint.h>

#define B_   4
#define H_   8
#define N_   2048
#define DV_  64
#define BH_  (B_ * H_)            // 32
#define COLS_ (BH_ * DV_)         // 2048 sort columns
#define OUT_ELEMS (BH_ * (size_t)N_ * DV_)
#define ATTN_ELEMS ((size_t)BH_ * N_ * N_)

// ---------------- scratch ----------------------------------------------------
__device__ uint32_t g_key [COLS_ * N_];   // sortable v, [bh][d][i]
__device__ float    g_vs  [COLS_ * N_];   // sorted values [bh][d][r]
__device__ uint16_t g_inv [COLS_ * N_];   // rank of orig index i
__device__ uint16_t g_p0  [BH_  * N_];    // p_0[r]
__device__ float    g_outt[COLS_ * N_];   // out in [bh][d][i] layout

__device__ __forceinline__ uint32_t f2sort(float x) {
    uint32_t u = __float_as_uint(x);
    return u ^ ((u & 0x80000000u) ? 0xFFFFFFFFu : 0x80000000u);
}
__device__ __forceinline__ float sort2f(uint32_t u) {
    u ^= (u & 0x80000000u) ? 0x80000000u : 0xFFFFFFFFu;
    return __uint_as_float(u);
}
__device__ __forceinline__ uint64_t cmpsel(uint64_t a, uint64_t y, bool keepmin) {
    return ((y < a) == keepmin) ? y : a;
}

// ---------------- 1) transpose v [bh][i][d] -> g_key [bh][d][i] --------------
__global__ void k_transpose_in(const float* __restrict__ v) {
    __shared__ float tile[32][33];
    int bh = blockIdx.z;
    int i0 = blockIdx.x * 32;
    int d0 = blockIdx.y * 32;
    int tx = threadIdx.x, ty = threadIdx.y;     // (32,8)
    const float* src = v + (size_t)bh * N_ * DV_;
#pragma unroll
    for (int r = 0; r < 32; r += 8)
        tile[ty + r][tx] = src[(size_t)(i0 + ty + r) * DV_ + (d0 + tx)];
    __syncthreads();
    uint32_t* dst = g_key + (size_t)bh * DV_ * N_;
#pragma unroll
    for (int r = 0; r < 32; r += 8)
        dst[(size_t)(d0 + ty + r) * N_ + (i0 + tx)] = f2sort(tile[tx][ty + r]);
}

// ---------------- bitonic merge tail, compile-time J -------------------------
template<int J>
__device__ __forceinline__ void merge_tail(uint64_t* x, int lane, int warp, int k) {
    if constexpr (J >= 8) {
        constexpr int LJ = J / 8;
#pragma unroll
        for (int r = 0; r < 8; r++) {
            int e = warp * 256 + lane * 8 + r;
            uint64_t y = __shfl_xor_sync(0xffffffffu, x[r], LJ);
            bool keepmin = (((lane & LJ) == 0) == ((e & k) == 0));
            x[r] = cmpsel(x[r], y, keepmin);
        }
    } else {
#pragma unroll
        for (int r = 0; r < 8; r++) {
            if ((r & J) == 0) {
                int e = warp * 256 + lane * 8 + r;
                bool up = ((e & k) == 0);
                uint64_t a = x[r], c = x[r + J];
                uint64_t mn = a < c ? a : c;
                uint64_t mx = a < c ? c : a;
                x[r]     = up ? mn : mx;
                x[r + J] = up ? mx : mn;
            }
        }
    }
    if constexpr (J > 1) merge_tail<J / 2>(x, lane, warp, k);
}

__device__ __forceinline__ void smem_stage(uint64_t* x, uint64_t* s,
                                           int g, int ebase, int j, int k) {
#pragma unroll
    for (int r = 0; r < 8; r += 2)
        *reinterpret_cast<ulonglong2*>(&s[10 * g + r]) =
            make_ulonglong2(x[r], x[r + 1]);
    __syncthreads();
    const int gp = g ^ (j >> 3);
    const bool upperbit = ((g & (j >> 3)) == 0);
    const bool kbit     = ((ebase & k) == 0);
    const bool keepmin  = (upperbit == kbit);
    uint64_t y[8];
#pragma unroll
    for (int r = 0; r < 8; r += 2) {
        ulonglong2 t2 = *reinterpret_cast<const ulonglong2*>(&s[10 * gp + r]);
        y[r] = t2.x; y[r + 1] = t2.y;
    }
#pragma unroll
    for (int r = 0; r < 8; r++)
        x[r] = cmpsel(x[r], y[r], keepmin);
    __syncthreads();
}

// ---------------- 2) fused: bitonic sort + attn zero-fill (R10 exact) --------
__global__ __launch_bounds__(256) void k_sortfill(float* __restrict__ attn) {
    const int col  = blockIdx.x;
    const int t    = threadIdx.x;
    const int lane = t & 31;
    const int warp = t >> 5;
    const int g    = warp * 32 + lane;
    const int ebase = g * 8;

    float4* __restrict__ fbase =
        reinterpret_cast<float4*>(attn) + (size_t)col * 16384 + t;
    const float4 z = make_float4(0.f, 0.f, 0.f, 0.f);
#define FILL4(c)                                                     \
    {  _Pragma("unroll")                                             \
       for (int s_ = 0; s_ < 4; s_++)                                \
           __stcs(fbase + (c) * 1024 + s_ * 256, z); }

    const uint32_t* __restrict__ key = g_key + (size_t)col * N_;

    FILL4(0)

    uint64_t x[8];
    {
        uint4 k0 = *reinterpret_cast<const uint4*>(key + ebase);
        uint4 k1 = *reinterpret_cast<const uint4*>(key + ebase + 4);
        x[0] = ((uint64_t)k0.x << 32) | (uint32_t)(ebase + 0);
        x[1] = ((uint64_t)k0.y << 32) | (uint32_t)(ebase + 1);
        x[2] = ((uint64_t)k0.z << 32) | (uint32_t)(ebase + 2);
        x[3] = ((uint64_t)k0.w << 32) | (uint32_t)(ebase + 3);
        x[4] = ((uint64_t)k1.x << 32) | (uint32_t)(ebase + 4);
        x[5] = ((uint64_t)k1.y << 32) | (uint32_t)(ebase + 5);
        x[6] = ((uint64_t)k1.z << 32) | (uint32_t)(ebase + 6);
        x[7] = ((uint64_t)k1.w << 32) | (uint32_t)(ebase + 7);
    }

    __shared__ uint64_t s[10 * 256];   // 20KB

    merge_tail<1>  (x, lane, warp, 2);
    merge_tail<2>  (x, lane, warp, 4);
    merge_tail<4>  (x, lane, warp, 8);
    FILL4(1)
    merge_tail<8>  (x, lane, warp, 16);
    FILL4(2)
    merge_tail<16> (x, lane, warp, 32);
    FILL4(3)
    merge_tail<32> (x, lane, warp, 64);
    FILL4(4)
    merge_tail<64> (x, lane, warp, 128);
    FILL4(5)
    merge_tail<128>(x, lane, warp, 256);
    FILL4(6)

    smem_stage(x, s, g, ebase, 256, 512);
    FILL4(7)
    merge_tail<128>(x, lane, warp, 512);
    FILL4(8)
    smem_stage(x, s, g, ebase, 512, 1024);
    FILL4(9)
    smem_stage(x, s, g, ebase, 256, 1024);
    FILL4(10)
    merge_tail<128>(x, lane, warp, 1024);
    FILL4(11)
    smem_stage(x, s, g, ebase, 1024, 2048);
    FILL4(12)
    smem_stage(x, s, g, ebase, 512, 2048);
    FILL4(13)
    smem_stage(x, s, g, ebase, 256, 2048);
    FILL4(14)
    merge_tail<128>(x, lane, warp, 2048);
    FILL4(15)

    // epilogue
    const int d  = col & 63;
    const int bh = col >> 6;
    float*    __restrict__ vs  = g_vs  + (size_t)col * N_;
    uint16_t* __restrict__ inv = g_inv + (size_t)col * N_;
    {
        float4 f0 = make_float4(sort2f((uint32_t)(x[0] >> 32)),
                                sort2f((uint32_t)(x[1] >> 32)),
                                sort2f((uint32_t)(x[2] >> 32)),
                                sort2f((uint32_t)(x[3] >> 32)));
        float4 f1 = make_float4(sort2f((uint32_t)(x[4] >> 32)),
                                sort2f((uint32_t)(x[5] >> 32)),
                                sort2f((uint32_t)(x[6] >> 32)),
                                sort2f((uint32_t)(x[7] >> 32)));
        *reinterpret_cast<float4*>(vs + ebase)     = f0;
        *reinterpret_cast<float4*>(vs + ebase + 4) = f1;
    }
#pragma unroll
    for (int r = 0; r < 8; r++) {
        uint32_t idx = (uint32_t)x[r];
        inv[idx] = (uint16_t)(ebase + r);
        if (d == 0) g_p0[bh * N_ + ebase + r] = (uint16_t)idx;
    }
#undef FILL4
}

// ---------------- 3) coalesced gather: out_t[col][i] = vs[col][inv1[i]] ------
__global__ __launch_bounds__(256) void k_gather() {
    __shared__ float svs[N_];
    const int col = blockIdx.x;            // bh*64 + d
    const int bh = col >> 6, d = col & 63;
    const int d1 = (d + 1) & 63;
    const float*    __restrict__ vs   = g_vs  + (size_t)col * N_;
    const uint16_t* __restrict__ inv1 = g_inv + (size_t)(bh * DV_ + d1) * N_;
    float*          __restrict__ ot   = g_outt + (size_t)col * N_;

    for (int i = threadIdx.x; i < N_; i += 256) svs[i] = vs[i];
    __syncthreads();
#pragma unroll
    for (int i = threadIdx.x; i < N_; i += 256)
        ot[i] = svs[inv1[i]];
}

// ---------------- 4) transpose g_outt [bh][d][i] -> out [bh][i][d] -----------
__global__ void k_transpose_out(float* __restrict__ out) {
    __shared__ float tile[32][33];
    int bh = blockIdx.z;
    int i0 = blockIdx.x * 32;
    int d0 = blockIdx.y * 32;
    int tx = threadIdx.x, ty = threadIdx.y;     // (32,8)
    const float* src = g_outt + (size_t)bh * DV_ * N_;
#pragma unroll
    for (int r = 0; r < 32; r += 8)
        tile[ty + r][tx] = src[(size_t)(d0 + ty + r) * N_ + (i0 + tx)];
    __syncthreads();
    float* dst = out + (size_t)bh * N_ * DV_;
#pragma unroll
    for (int r = 0; r < 32; r += 8)
        dst[(size_t)(i0 + ty + r) * DV_ + (d0 + tx)] = tile[tx][ty + r];
}

// ---------------- 5) attn scatter: attn[bh][i][ p0[inv1[i]] ] = 1 ------------
__global__ void k_attn(float* __restrict__ attn) {
    int gid = blockIdx.x * blockDim.x + threadIdx.x;   // bh*N + i
    int bh = gid >> 11;
    int i  = gid & (N_ - 1);
    int j    = g_inv[(size_t)(bh * DV_ + 1) * N_ + i];
    int aidx = g_p0[bh * N_ + j];
    attn[(size_t)gid * N_ + aidx] = 1.0f;
}

// ---------------- launch ------------------------------------------------------
extern "C" void kernel_launch(void* const* d_in, const int* in_sizes, int n_in,
                              void* d_out, int out_size) {
    (void)in_sizes; (void)n_in; (void)out_size;
    const float* v = (const float*)d_in[2];      // order: q, k, v
    float* out  = (float*)d_out;
    float* attn = out + OUT_ELEMS;

    k_transpose_in <<<dim3(N_ / 32, DV_ / 32, BH_), dim3(32, 8)>>>(v);
    k_sortfill     <<<COLS_, 256>>>(attn);
    k_attn         <<<(BH_ * N_) / 256, 256>>>(attn);
    k_gather       <<<COLS_, 256>>>();
    k_transpose_out<<<dim3(N_ / 32, DV_ / 32, BH_), dim3(32, 8)>>>(out);
}